// round 9
// baseline (speedup 1.0000x reference)
#include <cuda_runtime.h>
#include <cuda_bf16.h>
#include <cstdint>

#define N_IMG 64
#define IMG_ELEMS (3 * 512 * 512)          // 786432
#define BINS 256

#define THREADS 192                         // 6 warps
#define CHUNK   24576                       // elems per chunk; 128/thread -> u8 safe
#define CPI     (IMG_ELEMS / CHUNK)         // 32 chunks (sibling blocks) per image
#define NPAIRS  (N_IMG / 2)                 // 32 image pairs
#define NBLOCKS (NPAIRS * CPI)              // 1024 blocks
#define ITERS   (CHUNK / 4 / THREADS)       // 32 float4 iters per chunk
#define H_WORDS (THREADS * BINS / 4)        // 12288 u32 = 48 KB private hists
#define IDX_WORDS (CHUNK / 4)               // 6144 u32 = 24 KB idx for image A
#define DYN_SMEM ((H_WORDS + IDX_WORDS) * 4)  // 73728 B -> 3 blocks/SM

// ---------------- global coordination state -----------------------------------
__device__ unsigned int g_minmax[2 * N_IMG];   // enc(min), enc(max)
__device__ int g_hist[N_IMG * BINS];
__device__ int g_cnt1[N_IMG];                  // minmax arrivals
__device__ int g_cnt2[N_IMG];                  // hist arrivals

__device__ __forceinline__ unsigned fenc(float f) {
    unsigned u = __float_as_uint(f);
    return (u & 0x80000000u) ? ~u : (u | 0x80000000u);
}
__device__ __forceinline__ float fdec(unsigned u) {
    u = (u & 0x80000000u) ? (u ^ 0x80000000u) : ~u;
    return __uint_as_float(u);
}

// ---------------- k0: reset all coordination state (every replay!) ------------
__global__ void k_init() {
    int gt = blockIdx.x * 256 + threadIdx.x;       // 16384 = N_IMG*BINS
    g_hist[gt] = 0;
    if (gt < N_IMG) {
        g_minmax[gt] = 0xFFFFFFFFu;
        g_minmax[N_IMG + gt] = 0u;
        g_cnt1[gt] = 0;
        g_cnt2[gt] = 0;
    }
}

// ---- block minmax over one chunk; publishes atomics + arrival ----------------
__device__ __forceinline__ void phase_minmax(const float4* __restrict__ x,
                                             int base4, int t, int img,
                                             float* smn, float* smx) {
    float mn = 3.4e38f, mx = -3.4e38f;
#pragma unroll 8
    for (int i = 0; i < ITERS; i++) {
        float4 v = x[base4 + i * THREADS + t];
        mn = fminf(mn, fminf(fminf(v.x, v.y), fminf(v.z, v.w)));
        mx = fmaxf(mx, fmaxf(fmaxf(v.x, v.y), fmaxf(v.z, v.w)));
    }
#pragma unroll
    for (int o = 16; o > 0; o >>= 1) {
        mn = fminf(mn, __shfl_xor_sync(0xffffffffu, mn, o));
        mx = fmaxf(mx, __shfl_xor_sync(0xffffffffu, mx, o));
    }
    if ((t & 31) == 0) { smn[t >> 5] = mn; smx[t >> 5] = mx; }
    __syncthreads();
    if (t == 0) {
#pragma unroll
        for (int i = 1; i < 6; i++) {
            mn = fminf(mn, smn[i]);
            mx = fmaxf(mx, smx[i]);
        }
        atomicMin(&g_minmax[img], fenc(mn));
        atomicMax(&g_minmax[N_IMG + img], fenc(mx));
        __threadfence();
        atomicAdd(&g_cnt1[img], 1);
    }
    __syncthreads();                                  // smn/smx reusable after
}

// ---- spin until counter hits target (acquire) --------------------------------
__device__ __forceinline__ void spin_wait(int* cnt, int t) {
    if (t == 0) {
        while (*((volatile int*)cnt) < CPI) __nanosleep(64);
        __threadfence();
    }
    __syncthreads();
}

// ---- zero the 48 KB private hists --------------------------------------------
__device__ __forceinline__ void zero_hists(uint32_t* shw, int t) {
    uint4* shv = reinterpret_cast<uint4*>(shw);
#pragma unroll
    for (int i = 0; i < H_WORDS / 4 / THREADS; i++)
        shv[t + i * THREADS] = make_uint4(0, 0, 0, 0);
    __syncthreads();
}

// ---- reduce private hists -> g_hist[img], publish arrival --------------------
__device__ __forceinline__ void reduce_hists(uint32_t* shw, int t, int img) {
    int q = t & 63, g = t >> 6;                       // g in 0..2
    uint32_t s02 = 0, s13 = 0;
#pragma unroll
    for (int r = 0; r < 2; r++) {
        int w2 = g * 2 + r;
#pragma unroll 8
        for (int i = 0; i < 32; i++) {
            int l = (i + t) & 31;
            uint32_t v = shw[w2 * 2048 + q * 32 + l];
            s02 += v & 0x00FF00FFu;
            s13 += (v >> 8) & 0x00FF00FFu;
        }
    }
    __syncthreads();
    shw[t * 2] = s02;
    shw[t * 2 + 1] = s13;
    __syncthreads();
    if (t < 64) {
        uint32_t a02 = shw[t * 2]     + shw[(64 + t) * 2]     + shw[(128 + t) * 2];
        uint32_t a13 = shw[t * 2 + 1] + shw[(64 + t) * 2 + 1] + shw[(128 + t) * 2 + 1];
        int base = img * BINS + t * 4;
        atomicAdd(&g_hist[base + 0], (int)(a02 & 0xFFFFu));
        atomicAdd(&g_hist[base + 1], (int)(a13 & 0xFFFFu));
        atomicAdd(&g_hist[base + 2], (int)(a02 >> 16));
        atomicAdd(&g_hist[base + 3], (int)(a13 >> 16));
    }
    __syncthreads();
    if (t == 0) {
        __threadfence();
        atomicAdd(&g_cnt2[img], 1);
    }
    // no sync needed here; callers sync via later barriers
}

// ---- warp0 scans 256-bin cdf of img into lutf --------------------------------
__device__ __forceinline__ void build_lut(float* lutf, int t, int img) {
    if (t < 32) {
        int loc[8];
        int s = 0;
#pragma unroll
        for (int j = 0; j < 8; j++) {
            s += __ldcg(&g_hist[img * BINS + t * 8 + j]);
            loc[j] = s;                                // inclusive within lane
        }
        int sc = s;
#pragma unroll
        for (int o = 1; o < 32; o <<= 1) {
            int n = __shfl_up_sync(0xffffffffu, sc, (unsigned)o);
            if (t >= o) sc += n;
        }
        int excl = sc - s;
        float c0   = (float)__shfl_sync(0xffffffffu, loc[0], 0);  // cdf[0]
        float ctot = (float)__shfl_sync(0xffffffffu, sc, 31);     // cdf[255]
        float dinv = 1.0f / (ctot - c0 + 1e-8f);
#pragma unroll
        for (int j = 0; j < 8; j++)
            lutf[t * 8 + j] = ((float)(excl + loc[j]) - c0) * dinv;
    }
    __syncthreads();
}

// ---------------- fused paired-image equalize ---------------------------------
__global__ void __launch_bounds__(THREADS, 3)
k_equalize(const float4* __restrict__ x, float4* __restrict__ out) {
    extern __shared__ uint32_t smem[];
    uint32_t* shw  = smem;                  // 48 KB private hists / lut staging
    uint32_t* sidx = smem + H_WORDS;        // 24 KB idx for image A
    unsigned char* sh = reinterpret_cast<unsigned char*>(shw);
    float* lutf = reinterpret_cast<float*>(shw);

    int b = blockIdx.x, t = threadIdx.x;
    int p = b >> 5;                         // pair id 0..31
    int c = b & 31;                         // chunk id 0..31
    int imgA = 2 * p, imgB = 2 * p + 1;
    int baseA = imgA * (IMG_ELEMS / 4) + c * (CHUNK / 4);
    int baseB = imgB * (IMG_ELEMS / 4) + c * (CHUNK / 4);
    unsigned lane = t & 31u;
    unsigned wreg = (unsigned)(t >> 5);
    unsigned cbase = wreg * 8192u + lane * 4u;   // bank == lane hist column

    __shared__ float smn[6], smx[6];

    // ---- P1: minmax both chunks (B's pass hides A's barrier latency) ----
    phase_minmax(x, baseA, t, imgA, smn, smx);
    phase_minmax(x, baseB, t, imgB, smn, smx);

    zero_hists(shw, t);                     // more overlap before the A spin
    spin_wait(&g_cnt1[imgA], t);

    // ---- P2a: bucket A (L2-hot), idx -> smem, private hists ----
    {
        float gmn = fdec(__ldcg(&g_minmax[imgA]));
        float gmx = fdec(__ldcg(&g_minmax[N_IMG + imgA]));
        float inv = 1.0f / (gmx - gmn + 1e-8f);
#pragma unroll 8
        for (int i = 0; i < ITERS; i++) {
            float4 v = __ldcs(&x[baseA + i * THREADS + t]);
            unsigned b0 = (unsigned)(int)fminf(fmaxf((v.x - gmn) * 255.0f * inv, 0.0f), 255.0f);
            unsigned b1 = (unsigned)(int)fminf(fmaxf((v.y - gmn) * 255.0f * inv, 0.0f), 255.0f);
            unsigned b2 = (unsigned)(int)fminf(fmaxf((v.z - gmn) * 255.0f * inv, 0.0f), 255.0f);
            unsigned b3 = (unsigned)(int)fminf(fmaxf((v.w - gmn) * 255.0f * inv, 0.0f), 255.0f);
            sidx[i * THREADS + t] = b0 | (b1 << 8) | (b2 << 16) | (b3 << 24);
            sh[cbase + (b0 >> 2) * 128u + (b0 & 3u)]++;
            sh[cbase + (b1 >> 2) * 128u + (b1 & 3u)]++;
            sh[cbase + (b2 >> 2) * 128u + (b2 & 3u)]++;
            sh[cbase + (b3 >> 2) * 128u + (b3 & 3u)]++;
        }
        __syncthreads();
        reduce_hists(shw, t, imgA);
        __syncthreads();
    }

    zero_hists(shw, t);
    spin_wait(&g_cnt1[imgB], t);            // certainly done by now

    // ---- P2b: bucket B, idx -> registers, private hists ----
    uint32_t idxB[ITERS];
    {
        float gmn = fdec(__ldcg(&g_minmax[imgB]));
        float gmx = fdec(__ldcg(&g_minmax[N_IMG + imgB]));
        float inv = 1.0f / (gmx - gmn + 1e-8f);
#pragma unroll
        for (int i = 0; i < ITERS; i++) {
            float4 v = __ldcs(&x[baseB + i * THREADS + t]);
            unsigned b0 = (unsigned)(int)fminf(fmaxf((v.x - gmn) * 255.0f * inv, 0.0f), 255.0f);
            unsigned b1 = (unsigned)(int)fminf(fmaxf((v.y - gmn) * 255.0f * inv, 0.0f), 255.0f);
            unsigned b2 = (unsigned)(int)fminf(fmaxf((v.z - gmn) * 255.0f * inv, 0.0f), 255.0f);
            unsigned b3 = (unsigned)(int)fminf(fmaxf((v.w - gmn) * 255.0f * inv, 0.0f), 255.0f);
            idxB[i] = b0 | (b1 << 8) | (b2 << 16) | (b3 << 24);
            sh[cbase + (b0 >> 2) * 128u + (b0 & 3u)]++;
            sh[cbase + (b1 >> 2) * 128u + (b1 & 3u)]++;
            sh[cbase + (b2 >> 2) * 128u + (b2 & 3u)]++;
            sh[cbase + (b3 >> 2) * 128u + (b3 & 3u)]++;
        }
        __syncthreads();
        reduce_hists(shw, t, imgB);          // hides the imgA cnt2 spin below
        __syncthreads();
    }

    // ---- P4a: scan + gather + write image A ----
    spin_wait(&g_cnt2[imgA], t);            // mostly resolved during P2b
    build_lut(lutf, t, imgA);
#pragma unroll 8
    for (int i = 0; i < ITERS; i++) {
        uint32_t u = sidx[i * THREADS + t];
        float4 r;
        r.x = lutf[u & 0xFFu];
        r.y = lutf[(u >> 8) & 0xFFu];
        r.z = lutf[(u >> 16) & 0xFFu];
        r.w = lutf[u >> 24];
        __stcs(&out[baseA + i * THREADS + t], r);
    }
    __syncthreads();                        // lutf reused for B next

    // ---- P4b: scan + gather + write image B ----
    spin_wait(&g_cnt2[imgB], t);            // hidden by A's write stream
    build_lut(lutf, t, imgB);
#pragma unroll
    for (int i = 0; i < ITERS; i++) {
        uint32_t u = idxB[i];
        float4 r;
        r.x = lutf[u & 0xFFu];
        r.y = lutf[(u >> 8) & 0xFFu];
        r.z = lutf[(u >> 16) & 0xFFu];
        r.w = lutf[u >> 24];
        __stcs(&out[baseB + i * THREADS + t], r);
    }
}

// ---------------- launch -------------------------------------------------------
extern "C" void kernel_launch(void* const* d_in, const int* in_sizes, int n_in,
                              void* d_out, int out_size) {
    const float4* x = reinterpret_cast<const float4*>(d_in[0]);
    float4* out = reinterpret_cast<float4*>(d_out);

    static bool configured = false;
    if (!configured) {
        cudaFuncSetAttribute(k_equalize,
                             cudaFuncAttributeMaxDynamicSharedMemorySize, DYN_SMEM);
        configured = true;
    }
    k_init    <<<N_IMG, 256>>>();
    k_equalize<<<NBLOCKS, THREADS, DYN_SMEM>>>(x, out);
}

// round 10
// speedup vs baseline: 1.0911x; 1.0911x over previous
#include <cuda_runtime.h>
#include <cuda_bf16.h>
#include <cstdint>

#define N_IMG 64
#define IMG_ELEMS (3 * 512 * 512)          // 786432
#define BINS 256

#define THREADS 192                         // 6 warps
#define CHUNK   24576                       // 128 elems/thread -> u8 counts safe
#define CPI     (IMG_ELEMS / CHUNK)         // 32 sibling blocks per image
#define NBLOCKS (N_IMG * CPI)               // 2048
#define F4      (CHUNK / 4 / THREADS)       // 32 float4 (=128 floats) per thread
#define H_WORDS (THREADS * BINS / 4)        // 12288 u32 = 48 KB private hists
#define DYN_SMEM (H_WORDS * 4)              // 49152 B

// ---------------- global coordination state -----------------------------------
__device__ unsigned int g_minmax[2 * N_IMG];   // enc(min), enc(max)
__device__ int g_hist[N_IMG * BINS];
__device__ int g_cnt1[N_IMG];                  // minmax arrivals
__device__ int g_cnt2[N_IMG];                  // hist arrivals

__device__ __forceinline__ unsigned fenc(float f) {
    unsigned u = __float_as_uint(f);
    return (u & 0x80000000u) ? ~u : (u | 0x80000000u);
}
__device__ __forceinline__ float fdec(unsigned u) {
    u = (u & 0x80000000u) ? (u ^ 0x80000000u) : ~u;
    return __uint_as_float(u);
}

// ---------------- k0: reset all coordination state (every replay!) ------------
__global__ void k_init() {
    int gt = blockIdx.x * 256 + threadIdx.x;       // 16384 = N_IMG*BINS
    g_hist[gt] = 0;
    if (gt < N_IMG) {
        g_minmax[gt] = 0xFFFFFFFFu;
        g_minmax[N_IMG + gt] = 0u;
        g_cnt1[gt] = 0;
        g_cnt2[gt] = 0;
    }
}

// ---------------- fused equalize, x held in REGISTERS (single read) -----------
__global__ void __launch_bounds__(THREADS, 2)
k_equalize(const float4* __restrict__ x, float4* __restrict__ out) {
    extern __shared__ uint32_t shw[];               // 48 KB private hists, then lut
    unsigned char* sh = reinterpret_cast<unsigned char*>(shw);
    float* lutf = reinterpret_cast<float*>(shw);

    int b = blockIdx.x, t = threadIdx.x;
    int img = b / CPI;
    int base4 = b * (CHUNK / 4);
    unsigned lane = t & 31u;
    unsigned wreg = (unsigned)(t >> 5);
    unsigned cbase = wreg * 8192u + lane * 4u;       // bank == lane hist column

    __shared__ float smn[6], smx[6];

    // ---- P1: single read of x into registers; minmax from regs ----
    float4 xr[F4];
#pragma unroll
    for (int i = 0; i < F4; i++)
        xr[i] = __ldcs(&x[base4 + i * THREADS + t]);  // only read: evict-first

    float mn = 3.4e38f, mx = -3.4e38f;
#pragma unroll
    for (int i = 0; i < F4; i++) {
        float4 v = xr[i];
        mn = fminf(mn, fminf(fminf(v.x, v.y), fminf(v.z, v.w)));
        mx = fmaxf(mx, fmaxf(fmaxf(v.x, v.y), fmaxf(v.z, v.w)));
    }
#pragma unroll
    for (int o = 16; o > 0; o >>= 1) {
        mn = fminf(mn, __shfl_xor_sync(0xffffffffu, mn, o));
        mx = fmaxf(mx, __shfl_xor_sync(0xffffffffu, mx, o));
    }
    if (lane == 0) { smn[wreg] = mn; smx[wreg] = mx; }
    __syncthreads();
    if (t == 0) {
#pragma unroll
        for (int i = 1; i < 6; i++) {
            mn = fminf(mn, smn[i]);
            mx = fmaxf(mx, smx[i]);
        }
        atomicMin(&g_minmax[img], fenc(mn));
        atomicMax(&g_minmax[N_IMG + img], fenc(mx));
        __threadfence();
        atomicAdd(&g_cnt1[img], 1);
    }
    // zero private hists while waiting (overlaps the barrier)
    uint4* shv = reinterpret_cast<uint4*>(shw);
#pragma unroll
    for (int i = 0; i < H_WORDS / 4 / THREADS; i++)
        shv[t + i * THREADS] = make_uint4(0, 0, 0, 0);
    if (t == 0) {
        while (*((volatile int*)&g_cnt1[img]) < CPI) __nanosleep(64);
        __threadfence();
    }
    __syncthreads();

    float gmn = fdec(__ldcg(&g_minmax[img]));
    float gmx = fdec(__ldcg(&g_minmax[N_IMG + img]));
    float inv = 1.0f / (gmx - gmn + 1e-8f);

    // ---- P2: bucket straight from registers (x regs die into idx regs) ----
    uint32_t idxr[F4];
#pragma unroll
    for (int i = 0; i < F4; i++) {
        float4 v = xr[i];
        unsigned b0 = (unsigned)(int)fminf(fmaxf((v.x - gmn) * 255.0f * inv, 0.0f), 255.0f);
        unsigned b1 = (unsigned)(int)fminf(fmaxf((v.y - gmn) * 255.0f * inv, 0.0f), 255.0f);
        unsigned b2 = (unsigned)(int)fminf(fmaxf((v.z - gmn) * 255.0f * inv, 0.0f), 255.0f);
        unsigned b3 = (unsigned)(int)fminf(fmaxf((v.w - gmn) * 255.0f * inv, 0.0f), 255.0f);
        idxr[i] = b0 | (b1 << 8) | (b2 << 16) | (b3 << 24);
        sh[cbase + (b0 >> 2) * 128u + (b0 & 3u)]++;
        sh[cbase + (b1 >> 2) * 128u + (b1 & 3u)]++;
        sh[cbase + (b2 >> 2) * 128u + (b2 & 3u)]++;
        sh[cbase + (b3 >> 2) * 128u + (b3 & 3u)]++;
    }
    __syncthreads();

    // ---- P3: reduce private hists -> g_hist (lane-staggered, conflict-free) --
    {
        int q = t & 63, g = t >> 6;                       // g in 0..2
        uint32_t s02 = 0, s13 = 0;
#pragma unroll
        for (int r = 0; r < 2; r++) {
            int w2 = g * 2 + r;
#pragma unroll 8
            for (int i = 0; i < 32; i++) {
                int l = (i + t) & 31;
                uint32_t v = shw[w2 * 2048 + q * 32 + l];
                s02 += v & 0x00FF00FFu;
                s13 += (v >> 8) & 0x00FF00FFu;
            }
        }
        __syncthreads();
        shw[t * 2] = s02;
        shw[t * 2 + 1] = s13;
        __syncthreads();
        if (t < 64) {
            uint32_t a02 = shw[t * 2]     + shw[(64 + t) * 2]     + shw[(128 + t) * 2];
            uint32_t a13 = shw[t * 2 + 1] + shw[(64 + t) * 2 + 1] + shw[(128 + t) * 2 + 1];
            int base = img * BINS + t * 4;
            atomicAdd(&g_hist[base + 0], (int)(a02 & 0xFFFFu));
            atomicAdd(&g_hist[base + 1], (int)(a13 & 0xFFFFu));
            atomicAdd(&g_hist[base + 2], (int)(a02 >> 16));
            atomicAdd(&g_hist[base + 3], (int)(a13 >> 16));
        }
        __syncthreads();
        if (t == 0) {
            __threadfence();
            atomicAdd(&g_cnt2[img], 1);
            while (*((volatile int*)&g_cnt2[img]) < CPI) __nanosleep(64);
            __threadfence();
        }
        __syncthreads();
    }

    // ---- P4a: warp 0 scans the 256-bin cdf, LUT into smem ----
    if (t < 32) {
        int loc[8];
        int s = 0;
#pragma unroll
        for (int j = 0; j < 8; j++) {
            s += __ldcg(&g_hist[img * BINS + t * 8 + j]);
            loc[j] = s;                                    // inclusive within lane
        }
        int sc = s;
#pragma unroll
        for (int o = 1; o < 32; o <<= 1) {
            int n = __shfl_up_sync(0xffffffffu, sc, (unsigned)o);
            if (t >= o) sc += n;
        }
        int excl = sc - s;
        float c0   = (float)__shfl_sync(0xffffffffu, loc[0], 0);  // cdf[0]
        float ctot = (float)__shfl_sync(0xffffffffu, sc, 31);     // cdf[255]
        float dinv = 1.0f / (ctot - c0 + 1e-8f);
#pragma unroll
        for (int j = 0; j < 8; j++)
            lutf[t * 8 + j] = ((float)(excl + loc[j]) - c0) * dinv;
    }
    __syncthreads();

    // ---- P4b: gather from register idx, stream out ----
#pragma unroll
    for (int i = 0; i < F4; i++) {
        uint32_t u = idxr[i];
        float4 r;
        r.x = lutf[u & 0xFFu];
        r.y = lutf[(u >> 8) & 0xFFu];
        r.z = lutf[(u >> 16) & 0xFFu];
        r.w = lutf[u >> 24];
        __stcs(&out[base4 + i * THREADS + t], r);
    }
}

// ---------------- launch -------------------------------------------------------
extern "C" void kernel_launch(void* const* d_in, const int* in_sizes, int n_in,
                              void* d_out, int out_size) {
    const float4* x = reinterpret_cast<const float4*>(d_in[0]);
    float4* out = reinterpret_cast<float4*>(d_out);

    static bool configured = false;
    if (!configured) {
        cudaFuncSetAttribute(k_equalize,
                             cudaFuncAttributeMaxDynamicSharedMemorySize, DYN_SMEM);
        configured = true;
    }
    k_init    <<<N_IMG, 256>>>();
    k_equalize<<<NBLOCKS, THREADS, DYN_SMEM>>>(x, out);
}